// round 13
// baseline (speedup 1.0000x reference)
#include <cuda_runtime.h>
#include <cuda_fp16.h>
#include <cstdint>
#include <math.h>

// ---------------- problem constants ----------------
#define B_      4
#define P_      4096
#define FULL_   4096
#define SLICE_  512
#define EDIM_   1024
#define SLS_    1024          // slice start
#define FPMIN_  0.1875f
#define FPMAX_  0.4375f
#define KB_     512           // K for all GEMMs (fp16 hi only)

// ---------------- scratch (no allocs allowed) ----------------
__device__ __align__(16) __half g_A2[(size_t)B_ * P_ * KB_];    // gathered slice, fp16
__device__ __align__(16) __half g_B2[(size_t)3 * EDIM_ * KB_];  // Wq|Wk|Wv fp16
__device__ __align__(16) __half g_W1[(size_t)128 * KB_];        // W_g1 fp16
__device__ float g_scale[B_ * P_ + 256];
__device__ int   g_idx[P_];
__device__ __align__(16) float g_dirs[5 * EDIM_];

// ---------------- PTX helpers (sm_103-base-safe only) ----------------
__device__ __forceinline__ uint32_t smem_u32(const void* p) {
    uint32_t a; asm("{ .reg .u64 t; cvta.to.shared.u64 t, %1; cvt.u32.u64 %0, t; }" : "=r"(a) : "l"(p)); return a;
}
#define CP_ASYNC16(dst, src) \
    asm volatile("cp.async.cg.shared.global [%0], [%1], 16;" :: "r"(dst), "l"(src))
#define CP_COMMIT() asm volatile("cp.async.commit_group;" ::: "memory")
#define CP_WAIT1()  asm volatile("cp.async.wait_group 1;" ::: "memory")

#define LDSM4(r0, r1, r2, r3, a) \
    asm volatile("ldmatrix.sync.aligned.m8n8.x4.shared.b16 {%0,%1,%2,%3}, [%4];" \
        : "=r"(r0), "=r"(r1), "=r"(r2), "=r"(r3) : "r"(a))

#define MMA16816(c, a, b0, b1) \
    asm volatile("mma.sync.aligned.m16n8k16.row.col.f32.f16.f16.f32 " \
        "{%0,%1,%2,%3},{%4,%5,%6,%7},{%8,%9},{%0,%1,%2,%3};" \
        : "+f"((c)[0]), "+f"((c)[1]), "+f"((c)[2]), "+f"((c)[3]) \
        : "r"((a)[0]), "r"((a)[1]), "r"((a)[2]), "r"((a)[3]), "r"(b0), "r"(b1))

__device__ __forceinline__ uint32_t swz(uint32_t row, uint32_t bytecol) {
    return row * 128u + (bytecol ^ ((row & 7u) << 4));
}

// =====================================================================
// K1: small prep, 1024 threads/block.
//   Block 0: fast compaction (warp-shuffle scan, 4 fps/thread) + dirs.
//   Blocks 1..16: W_g1 -> g_W1 fp16 (needed by K2's gate blocks)
// =====================================================================
__global__ void k_prep(const float* __restrict__ fps,
                       const float* __restrict__ penta,
                       const float* __restrict__ W_g1)
{
    int t = threadIdx.x;
    int bid = blockIdx.x;
    if (bid >= 1) {                        // W1: 128 rows x 128 quads
        int id = (bid - 1) * 1024 + t;     // 0..16383
        int n  = id >> 7;
        int k4 = (id & 127) * 4;
        float4 v = *(const float4*)(W_g1 + (size_t)n * 512 + k4);
        __half2* d = (__half2*)(g_W1 + (size_t)n * KB_ + k4);
        d[0] = __half2(__float2half(v.x), __float2half(v.y));
        d[1] = __half2(__float2half(v.z), __float2half(v.w));
        return;
    }

    // ---- block 0: compaction via warp-shuffle scan ----
    __shared__ int warp_s[32];
    int lane = t & 31, w = t >> 5;
    float4 f = *(const float4*)(fps + t * 4);
    unsigned m0 = (f.x >= FPMIN_ && f.x < FPMAX_) ? 1u : 0u;
    unsigned m1 = (f.y >= FPMIN_ && f.y < FPMAX_) ? 1u : 0u;
    unsigned m2 = (f.z >= FPMIN_ && f.z < FPMAX_) ? 1u : 0u;
    unsigned m3 = (f.w >= FPMIN_ && f.w < FPMAX_) ? 1u : 0u;
    int cnt = (int)(m0 + m1 + m2 + m3);
    int inc = cnt;
    #pragma unroll
    for (int o = 1; o < 32; o <<= 1) {
        int x = __shfl_up_sync(0xffffffffu, inc, o);
        if (lane >= o) inc += x;
    }
    if (lane == 31) warp_s[w] = inc;
    __syncthreads();
    if (w == 0) {
        int v = warp_s[lane];
        int iv = v;
        #pragma unroll
        for (int o = 1; o < 32; o <<= 1) {
            int x = __shfl_up_sync(0xffffffffu, iv, o);
            if (lane >= o) iv += x;
        }
        warp_s[lane] = iv - v;   // exclusive warp base
    }
    __syncthreads();
    int off = warp_s[w] + inc - cnt;
    int base = t * 4;
    if (m0) g_idx[off++] = base;
    if (m1) g_idx[off++] = base + 1;
    if (m2) g_idx[off++] = base + 2;
    if (m3) g_idx[off++] = base + 3;

    // ---- dirs normalization (5 warps) ----
    if (t < 160) {
        int wv = t >> 5, ln = t & 31;
        float s = 0.f;
        #pragma unroll
        for (int kk = 0; kk < 32; ++kk) {
            float x = penta[wv * EDIM_ + kk * 32 + ln];
            s += x * x;
        }
        #pragma unroll
        for (int o = 16; o >= 1; o >>= 1) s += __shfl_xor_sync(0xffffffffu, s, o);
        float inv = rsqrtf(s);
        #pragma unroll
        for (int kk = 0; kk < 32; ++kk) {
            int id = wv * EDIM_ + kk * 32 + ln;
            g_dirs[id] = penta[id] * inv;
        }
    }
}

// =====================================================================
// K2: fused gather + gate. 32 rows/block, 256 thr, 2 CTAs/SM.
// smem: A resident 32KB | W1 3-stage pipeline 3 x 16KB -> 80KB total
// Tail work per block (grid-stride): Wq/Wk/Wv -> g_B2 fp16 conversion +
// zero the projection region of out (both consumed only by K3).
// =====================================================================
#define GA_SM   32768
#define GW_STG  16384
#define GSMEM   (GA_SM + 3 * GW_STG)     // 81920
__global__ void __launch_bounds__(256, 2)
k_gategather(const float* __restrict__ tokens,
             const float* __restrict__ b_g1,
             const float* __restrict__ W_g2,
             const float* __restrict__ b_g2,
             const float* __restrict__ alphap,
             const float* __restrict__ Wq,
             const float* __restrict__ Wk,
             const float* __restrict__ Wv,
             float* __restrict__ out,
             int N, int M)
{
    extern __shared__ char gsm[];
    const uint32_t sbase = smem_u32(gsm);
    const int tid = threadIdx.x, lane = tid & 31, wid = tid >> 5;
    const int wm = wid & 1, wn = wid >> 1;     // 2 x 4 warps -> 32x128
    const int m0 = blockIdx.x * 32;

    // ---- W1 pipeline prologue: stages 0,1 ----
    #pragma unroll
    for (int pre = 0; pre < 2; ++pre) {
        uint32_t wb = sbase + GA_SM + pre * GW_STG;
        #pragma unroll
        for (int i = 0; i < 4; ++i) {
            int u = tid + i * 256;
            int rowB = u >> 3, kc = (u & 7) * 8;
            CP_ASYNC16(wb + swz((uint32_t)rowB, (uint32_t)kc * 2),
                       (const void*)(g_W1 + (size_t)rowB * KB_ + pre * 64 + kc));
        }
        CP_COMMIT();
    }

    // ---- A: gather + convert ----
    {
        int r = tid >> 3, ch = tid & 7;
        int gr = m0 + r;
        const float4* src = nullptr;
        if (gr < M) {
            int b = gr / N, j = gr - b * N;
            int p = g_idx[j];
            src = (const float4*)(tokens + ((size_t)b * P_ + p) * FULL_ + SLS_ + ch * 64);
        }
        __half2 hv[32];
        #pragma unroll
        for (int i = 0; i < 16; ++i) {
            float4 v = src ? src[i] : make_float4(0.f, 0.f, 0.f, 0.f);
            hv[2 * i]     = __half2(__float2half(v.x), __float2half(v.y));
            hv[2 * i + 1] = __half2(__float2half(v.z), __float2half(v.w));
        }
        #pragma unroll
        for (int u = 0; u < 8; ++u) {
            uint32_t o = (uint32_t)(ch * 4096) + swz((uint32_t)r, (uint32_t)(u * 16));
            *(uint4*)(gsm + o) = *(uint4*)&hv[u * 4];
        }
        __half* gdst = g_A2 + (size_t)gr * KB_ + ch * 64;
        #pragma unroll
        for (int u = 0; u < 8; ++u)
            *(uint4*)(gdst + u * 8) = *(uint4*)&hv[u * 4];
    }

    // ---- MMA: h[32,128] = A @ W1^T, W1 pipelined ----
    float acc[2][2][4];
    #pragma unroll
    for (int p = 0; p < 2; ++p)
        #pragma unroll
        for (int j = 0; j < 2; ++j)
            #pragma unroll
            for (int q = 0; q < 4; ++q) acc[p][j][q] = 0.f;

    #pragma unroll 1
    for (int s = 0; s < 8; ++s) {
        CP_WAIT1();
        __syncthreads();
        if (s + 2 < 8) {
            uint32_t wb = sbase + GA_SM + ((s + 2) % 3) * GW_STG;
            #pragma unroll
            for (int i = 0; i < 4; ++i) {
                int u = tid + i * 256;
                int rowB = u >> 3, kc = (u & 7) * 8;
                CP_ASYNC16(wb + swz((uint32_t)rowB, (uint32_t)kc * 2),
                           (const void*)(g_W1 + (size_t)rowB * KB_ + (s + 2) * 64 + kc));
            }
        }
        CP_COMMIT();

        const uint32_t aBase = sbase + s * 4096;
        const uint32_t bBase = sbase + GA_SM + (s % 3) * GW_STG;
        const uint32_t rowA = wm * 16 + (lane & 15);
        #pragma unroll
        for (int kk = 0; kk < 4; ++kk) {
            uint32_t a[4];
            uint32_t bcA = kk * 32 + (lane >> 4) * 16;
            LDSM4(a[0], a[1], a[2], a[3], aBase + swz(rowA, bcA));
            #pragma unroll
            for (int p = 0; p < 2; ++p) {
                uint32_t rowB = wn * 32 + p * 16 + ((lane >> 4) & 1) * 8 + (lane & 7);
                uint32_t bcB = kk * 32 + ((lane >> 3) & 1) * 16;
                uint32_t b0, b1, b2, b3;
                LDSM4(b0, b1, b2, b3, bBase + swz(rowB, bcB));
                MMA16816(acc[p][0], a, b0, b1);
                MMA16816(acc[p][1], a, b2, b3);
            }
        }
        __syncthreads();
    }

    // ---- h tile -> smem ----
    float* hs = (float*)gsm;   // [32][132]
    {
        int r0h = wm * 16 + (lane >> 2);
        int cb  = wn * 32 + (lane & 3) * 2;
        #pragma unroll
        for (int p = 0; p < 2; ++p)
            #pragma unroll
            for (int j = 0; j < 2; ++j) {
                int cc = cb + p * 16 + j * 8;
                hs[r0h * 132 + cc]           = acc[p][j][0];
                hs[r0h * 132 + cc + 1]       = acc[p][j][1];
                hs[(r0h + 8) * 132 + cc]     = acc[p][j][2];
                hs[(r0h + 8) * 132 + cc + 1] = acc[p][j][3];
            }
    }
    __syncthreads();

    // ---- GELU + dot(w2) + sigmoid -> scale ----
    float aw = 1.f / (1.f + expf(-alphap[0]));
    #pragma unroll
    for (int rr = 0; rr < 4; ++rr) {
        int r = wid * 4 + rr;
        float s = 0.f;
        #pragma unroll
        for (int q = 0; q < 4; ++q) {
            int cc = lane + 32 * q;
            float x = hs[r * 132 + cc] + b_g1[cc];
            float h = 0.5f * x * (1.f + erff(x * 0.70710678118654752f));
            s += h * W_g2[cc];
        }
        #pragma unroll
        for (int o = 16; o >= 1; o >>= 1) s += __shfl_xor_sync(0xffffffffu, s, o);
        if (lane == 0) {
            float gate = 1.f / (1.f + expf(-(s + b_g2[0])));
            g_scale[m0 + r] = gate * aw + (1.f - aw);
        }
    }

    // ---- tail: B2 conversion (3072 rows x 128 quads), grid-stride ----
    {
        const int G = gridDim.x;
        for (int id = blockIdx.x * 256 + tid; id < 3072 * 128; id += G * 256) {
            int n  = id >> 7;
            int k4 = (id & 127) * 4;
            const float* W;
            int nn;
            if (n < 1024)      { W = Wq; nn = n; }
            else if (n < 2048) { W = Wk; nn = n - 1024; }
            else               { W = Wv; nn = n - 2048; }
            float4 v = *(const float4*)(W + (size_t)nn * 512 + k4);
            __half2* d = (__half2*)(g_B2 + (size_t)n * KB_ + k4);
            d[0] = __half2(__float2half(v.x), __float2half(v.y));
            d[1] = __half2(__float2half(v.z), __float2half(v.w));
        }
        // ---- tail: zero projection region of out ----
        long long tot4 = (long long)15 * M / 4;
        float4* dst = (float4*)(out + (size_t)3 * M * EDIM_);
        for (long long i4 = (long long)blockIdx.x * 256 + tid; i4 < tot4;
             i4 += (long long)G * 256)
            dst[i4] = make_float4(0.f, 0.f, 0.f, 0.f);
    }
}

// =====================================================================
// K3: main HMMA GEMM C[Mpad,3072] = A@B^T (K=512), scaled epilogue
//     (streaming stores) + pentachoron partials atomicAdd'ed into d_out.
// =====================================================================
#define TILE_B    16384
#define STAGE_B2  (2 * TILE_B)
#define NSTAGE    3
#define GEMM_SMEM (NSTAGE * STAGE_B2)    // 98304
#define NS        (KB_ / 64)             // 8

__global__ void __launch_bounds__(256, 2)
k_gemm_mma(float* __restrict__ out, int M)
{
    extern __shared__ char smem[];
    const uint32_t sb = smem_u32(smem);
    const int tid = threadIdx.x, lane = tid & 31;
    const int wid = tid >> 5;
    const int wm = wid & 3, wn = wid >> 2;          // 4 x 2 warp grid
    const int m0 = blockIdx.y * 128;
    const int n0 = blockIdx.x * 128;

    const __half* Ag = g_A2 + (size_t)m0 * KB_;
    const __half* Bg = g_B2 + (size_t)n0 * KB_;

    const int ldRow = tid >> 3, ldCh = (tid & 7) * 8;

    float acc[2][8][4];
    #pragma unroll
    for (int h = 0; h < 2; ++h)
        #pragma unroll
        for (int j = 0; j < 8; ++j)
            #pragma unroll
            for (int q = 0; q < 4; ++q) acc[h][j][q] = 0.f;

    #pragma unroll
    for (int pre = 0; pre < 2; ++pre) {
        uint32_t base = sb + pre * STAGE_B2;
        #pragma unroll
        for (int i = 0; i < 4; ++i) {
            int row = ldRow + i * 32;
            uint32_t doff = swz(row, ldCh * 2);
            CP_ASYNC16(base + doff, (const void*)(Ag + (size_t)row * KB_ + pre * 64 + ldCh));
            CP_ASYNC16(base + TILE_B + doff, (const void*)(Bg + (size_t)row * KB_ + pre * 64 + ldCh));
        }
        CP_COMMIT();
    }

    #pragma unroll 1
    for (int s = 0; s < NS; ++s) {
        CP_WAIT1();
        __syncthreads();
        if (s + 2 < NS) {
            uint32_t base = sb + ((s + 2) % NSTAGE) * STAGE_B2;
            #pragma unroll
            for (int i = 0; i < 4; ++i) {
                int row = ldRow + i * 32;
                uint32_t doff = swz(row, ldCh * 2);
                CP_ASYNC16(base + doff, (const void*)(Ag + (size_t)row * KB_ + (s + 2) * 64 + ldCh));
                CP_ASYNC16(base + TILE_B + doff, (const void*)(Bg + (size_t)row * KB_ + (s + 2) * 64 + ldCh));
            }
        }
        CP_COMMIT();

        const uint32_t stg = sb + (s % NSTAGE) * STAGE_B2;
        const uint32_t rowA0 = wm * 32 + (lane & 15);
        const uint32_t aRB0 = stg + rowA0 * 128, xrA0 = (rowA0 & 7u) << 4;
        const uint32_t aRB1 = aRB0 + 16 * 128;
        #pragma unroll
        for (int kk = 0; kk < 4; ++kk) {
            uint32_t a0[4], a1[4];
            uint32_t bcA = kk * 32 + (lane >> 4) * 16;
            LDSM4(a0[0], a0[1], a0[2], a0[3], aRB0 + (bcA ^ xrA0));
            LDSM4(a1[0], a1[1], a1[2], a1[3], aRB1 + (bcA ^ xrA0));
            #pragma unroll
            for (int p = 0; p < 4; ++p) {
                uint32_t rowB = wn * 64 + p * 16 + ((lane >> 4) & 1) * 8 + (lane & 7);
                uint32_t bcB = kk * 32 + ((lane >> 3) & 1) * 16;
                uint32_t b0, b1, b2, b3;
                LDSM4(b0, b1, b2, b3, stg + TILE_B + swz(rowB, bcB));
                MMA16816(acc[0][2 * p],     a0, b0, b1);
                MMA16816(acc[0][2 * p + 1], a0, b2, b3);
                MMA16816(acc[1][2 * p],     a1, b0, b1);
                MMA16816(acc[1][2 * p + 1], a1, b2, b3);
            }
        }
        __syncthreads();
    }

    // ---- dirs slice into smem ----
    float* ds = (float*)smem;            // [5][128]
    const int ncol0 = n0 & 1023;
    for (int i = tid; i < 640; i += 256) {
        int v = i >> 7, l = i & 127;
        ds[i] = g_dirs[v * EDIM_ + ncol0 + l];
    }
    __syncthreads();

    // ---- epilogue: scale, streaming store, proj partials -> atomicAdd ----
    const int sel  = n0 >> 10;
    const int ncolB = ncol0 + wn * 64;
    float* outM = out + (size_t)sel * M * EDIM_;
    float* projM = out + (size_t)3 * M * EDIM_ + (size_t)sel * 5 * M;
    #pragma unroll
    for (int h = 0; h < 2; ++h) {
        #pragma unroll
        for (int rr = 0; rr < 2; ++rr) {
            int grow = m0 + wm * 32 + h * 16 + rr * 8 + (lane >> 2);
            float sc = g_scale[grow];
            bool ok = grow < M;
            float* orow = outM + (size_t)grow * EDIM_ + ncolB + 2 * (lane & 3);
            float p0 = 0.f, p1 = 0.f, p2 = 0.f, p3 = 0.f, p4 = 0.f;
            #pragma unroll
            for (int j = 0; j < 8; ++j) {
                float c0 = acc[h][j][2 * rr] * sc;
                float c1 = acc[h][j][2 * rr + 1] * sc;
                if (ok) __stcs((float2*)(orow + j * 8), make_float2(c0, c1));
                int lc = wn * 64 + j * 8 + 2 * (lane & 3);
                p0 += c0 * ds[lc]       + c1 * ds[lc + 1];
                p1 += c0 * ds[128 + lc] + c1 * ds[128 + lc + 1];
                p2 += c0 * ds[256 + lc] + c1 * ds[256 + lc + 1];
                p3 += c0 * ds[384 + lc] + c1 * ds[384 + lc + 1];
                p4 += c0 * ds[512 + lc] + c1 * ds[512 + lc + 1];
            }
            p0 += __shfl_xor_sync(0xffffffffu, p0, 1); p0 += __shfl_xor_sync(0xffffffffu, p0, 2);
            p1 += __shfl_xor_sync(0xffffffffu, p1, 1); p1 += __shfl_xor_sync(0xffffffffu, p1, 2);
            p2 += __shfl_xor_sync(0xffffffffu, p2, 1); p2 += __shfl_xor_sync(0xffffffffu, p2, 2);
            p3 += __shfl_xor_sync(0xffffffffu, p3, 1); p3 += __shfl_xor_sync(0xffffffffu, p3, 2);
            p4 += __shfl_xor_sync(0xffffffffu, p4, 1); p4 += __shfl_xor_sync(0xffffffffu, p4, 2);
            if (ok && (lane & 3) == 0) {
                atomicAdd(projM + 0 * (size_t)M + grow, p0);
                atomicAdd(projM + 1 * (size_t)M + grow, p1);
                atomicAdd(projM + 2 * (size_t)M + grow, p2);
                atomicAdd(projM + 3 * (size_t)M + grow, p3);
                atomicAdd(projM + 4 * (size_t)M + grow, p4);
            }
        }
    }
}

// =====================================================================
extern "C" void kernel_launch(void* const* d_in, const int* in_sizes, int n_in,
                              void* d_out, int out_size)
{
    const float* tokens = (const float*)d_in[0];
    const float* fps    = (const float*)d_in[1];
    const float* W_g1   = (const float*)d_in[2];
    const float* b_g1   = (const float*)d_in[3];
    const float* W_g2   = (const float*)d_in[4];
    const float* b_g2   = (const float*)d_in[5];
    const float* alpha  = (const float*)d_in[6];
    const float* Wq     = (const float*)d_in[7];
    const float* Wk     = (const float*)d_in[8];
    const float* Wv     = (const float*)d_in[9];
    const float* penta  = (const float*)d_in[10];

    int N = out_size / 12348;       // per token: 3*1024 QKV + 3*5 projections
    if (N <= 0) return;
    int M = 4 * N;
    int Mpad = (M + 127) & ~127;
    float* out = (float*)d_out;

    cudaFuncSetAttribute(k_gemm_mma, cudaFuncAttributeMaxDynamicSharedMemorySize, GEMM_SMEM);
    cudaFuncSetAttribute(k_gategather, cudaFuncAttributeMaxDynamicSharedMemorySize, GSMEM);

    k_prep<<<17, 1024>>>(fps, penta, W_g1);
    k_gategather<<<Mpad / 32, 256, GSMEM>>>(tokens, b_g1, W_g2, b_g2, alpha,
                                            Wq, Wk, Wv, out, N, M);
    dim3 g3(24, Mpad / 128);
    k_gemm_mma<<<g3, 256, GEMM_SMEM>>>(out, M);
}

// round 14
// speedup vs baseline: 1.0292x; 1.0292x over previous
#include <cuda_runtime.h>
#include <cuda_fp16.h>
#include <cstdint>
#include <math.h>

// ---------------- problem constants ----------------
#define B_      4
#define P_      4096
#define FULL_   4096
#define SLICE_  512
#define EDIM_   1024
#define SLS_    1024          // slice start
#define FPMIN_  0.1875f
#define FPMAX_  0.4375f
#define KB_     512           // K for all GEMMs (fp16 hi only)

// ---------------- scratch (no allocs allowed) ----------------
__device__ __align__(16) __half g_A2[(size_t)B_ * P_ * KB_];    // gathered slice, fp16
__device__ __align__(16) __half g_B2[(size_t)3 * EDIM_ * KB_];  // Wq|Wk|Wv fp16
__device__ __align__(16) __half g_W1[(size_t)128 * KB_];        // W_g1 fp16
__device__ float g_scale[B_ * P_ + 256];
__device__ int   g_idx[P_];
__device__ __align__(16) float g_dirs[5 * EDIM_];

// ---------------- PTX helpers (sm_103-base-safe only) ----------------
__device__ __forceinline__ uint32_t smem_u32(const void* p) {
    uint32_t a; asm("{ .reg .u64 t; cvta.to.shared.u64 t, %1; cvt.u32.u64 %0, t; }" : "=r"(a) : "l"(p)); return a;
}
#define CP_ASYNC16(dst, src) \
    asm volatile("cp.async.cg.shared.global [%0], [%1], 16;" :: "r"(dst), "l"(src))
#define CP_COMMIT() asm volatile("cp.async.commit_group;" ::: "memory")
#define CP_WAIT1()  asm volatile("cp.async.wait_group 1;" ::: "memory")

#define LDSM4(r0, r1, r2, r3, a) \
    asm volatile("ldmatrix.sync.aligned.m8n8.x4.shared.b16 {%0,%1,%2,%3}, [%4];" \
        : "=r"(r0), "=r"(r1), "=r"(r2), "=r"(r3) : "r"(a))

#define MMA16816(c, a, b0, b1) \
    asm volatile("mma.sync.aligned.m16n8k16.row.col.f32.f16.f16.f32 " \
        "{%0,%1,%2,%3},{%4,%5,%6,%7},{%8,%9},{%0,%1,%2,%3};" \
        : "+f"((c)[0]), "+f"((c)[1]), "+f"((c)[2]), "+f"((c)[3]) \
        : "r"((a)[0]), "r"((a)[1]), "r"((a)[2]), "r"((a)[3]), "r"(b0), "r"(b1))

__device__ __forceinline__ uint32_t swz(uint32_t row, uint32_t bytecol) {
    return row * 128u + (bytecol ^ ((row & 7u) << 4));
}

// =====================================================================
// K1: merged prep, 1024 threads/block, 4 quads/thread (MLP=4).
//   Block 0: compaction (warp-shuffle scan) + dirs.
//   Blocks 1..4:      W_g1 -> g_W1 fp16        (16384 quads)
//   Blocks 5..100:    Wq|Wk|Wv -> g_B2 fp16    (393216 quads)
//   Blocks 101+:      zero projection region of out (4096 f4/block)
// =====================================================================
__global__ void k_prep(const float* __restrict__ fps,
                       const float* __restrict__ penta,
                       const float* __restrict__ Wq,
                       const float* __restrict__ Wk,
                       const float* __restrict__ Wv,
                       const float* __restrict__ W_g1,
                       float* __restrict__ out, int M)
{
    int t = threadIdx.x;
    int bid = blockIdx.x;
    if (bid >= 101) {
        long long base4 = (long long)(bid - 101) * 4096 + t;
        long long tot4 = (long long)15 * M / 4;
        float4* dst = (float4*)(out + (size_t)3 * M * EDIM_);
        #pragma unroll
        for (int i = 0; i < 4; ++i) {
            long long i4 = base4 + (long long)i * 1024;
            if (i4 < tot4) dst[i4] = make_float4(0.f, 0.f, 0.f, 0.f);
        }
        return;
    }
    if (bid >= 5) {                        // B2: 3072 rows x 128 quads
        int id0 = (bid - 5) * 4096 + t;
        float4 v[4];
        int ids[4];
        #pragma unroll
        for (int i = 0; i < 4; ++i) {
            int id = id0 + i * 1024;       // < 393216 always (96 blocks exact)
            ids[i] = id;
            int n  = id >> 7;
            int k4 = (id & 127) * 4;
            const float* W;
            int nn;
            if (n < 1024)      { W = Wq; nn = n; }
            else if (n < 2048) { W = Wk; nn = n - 1024; }
            else               { W = Wv; nn = n - 2048; }
            v[i] = *(const float4*)(W + (size_t)nn * 512 + k4);
        }
        #pragma unroll
        for (int i = 0; i < 4; ++i) {
            int n  = ids[i] >> 7;
            int k4 = (ids[i] & 127) * 4;
            __half2* d = (__half2*)(g_B2 + (size_t)n * KB_ + k4);
            d[0] = __half2(__float2half(v[i].x), __float2half(v[i].y));
            d[1] = __half2(__float2half(v[i].z), __float2half(v[i].w));
        }
        return;
    }
    if (bid >= 1) {                        // W1: 128 rows x 128 quads
        int id0 = (bid - 1) * 4096 + t;
        float4 v[4];
        #pragma unroll
        for (int i = 0; i < 4; ++i) {
            int id = id0 + i * 1024;       // < 16384 always (4 blocks exact)
            int n  = id >> 7;
            int k4 = (id & 127) * 4;
            v[i] = *(const float4*)(W_g1 + (size_t)n * 512 + k4);
        }
        #pragma unroll
        for (int i = 0; i < 4; ++i) {
            int id = id0 + i * 1024;
            int n  = id >> 7;
            int k4 = (id & 127) * 4;
            __half2* d = (__half2*)(g_W1 + (size_t)n * KB_ + k4);
            d[0] = __half2(__float2half(v[i].x), __float2half(v[i].y));
            d[1] = __half2(__float2half(v[i].z), __float2half(v[i].w));
        }
        return;
    }

    // ---- block 0: compaction via warp-shuffle scan ----
    __shared__ int warp_s[32];
    int lane = t & 31, w = t >> 5;
    float4 f = *(const float4*)(fps + t * 4);
    unsigned m0 = (f.x >= FPMIN_ && f.x < FPMAX_) ? 1u : 0u;
    unsigned m1 = (f.y >= FPMIN_ && f.y < FPMAX_) ? 1u : 0u;
    unsigned m2 = (f.z >= FPMIN_ && f.z < FPMAX_) ? 1u : 0u;
    unsigned m3 = (f.w >= FPMIN_ && f.w < FPMAX_) ? 1u : 0u;
    int cnt = (int)(m0 + m1 + m2 + m3);
    int inc = cnt;
    #pragma unroll
    for (int o = 1; o < 32; o <<= 1) {
        int x = __shfl_up_sync(0xffffffffu, inc, o);
        if (lane >= o) inc += x;
    }
    if (lane == 31) warp_s[w] = inc;
    __syncthreads();
    if (w == 0) {
        int v = warp_s[lane];
        int iv = v;
        #pragma unroll
        for (int o = 1; o < 32; o <<= 1) {
            int x = __shfl_up_sync(0xffffffffu, iv, o);
            if (lane >= o) iv += x;
        }
        warp_s[lane] = iv - v;   // exclusive warp base
    }
    __syncthreads();
    int off = warp_s[w] + inc - cnt;
    int base = t * 4;
    if (m0) g_idx[off++] = base;
    if (m1) g_idx[off++] = base + 1;
    if (m2) g_idx[off++] = base + 2;
    if (m3) g_idx[off++] = base + 3;

    // ---- dirs normalization (5 warps) ----
    if (t < 160) {
        int wv = t >> 5, ln = t & 31;
        float s = 0.f;
        #pragma unroll
        for (int kk = 0; kk < 32; ++kk) {
            float x = penta[wv * EDIM_ + kk * 32 + ln];
            s += x * x;
        }
        #pragma unroll
        for (int o = 16; o >= 1; o >>= 1) s += __shfl_xor_sync(0xffffffffu, s, o);
        float inv = rsqrtf(s);
        #pragma unroll
        for (int kk = 0; kk < 32; ++kk) {
            int id = wv * EDIM_ + kk * 32 + ln;
            g_dirs[id] = penta[id] * inv;
        }
    }
}

// =====================================================================
// K2: fused gather + gate. 32 rows/block, 256 thr, 2 CTAs/SM. (round-10)
// smem: A resident 32KB | W1 3-stage pipeline 3 x 16KB -> 80KB total
// =====================================================================
#define GA_SM   32768
#define GW_STG  16384
#define GSMEM   (GA_SM + 3 * GW_STG)     // 81920
__global__ void __launch_bounds__(256, 2)
k_gategather(const float* __restrict__ tokens,
             const float* __restrict__ b_g1,
             const float* __restrict__ W_g2,
             const float* __restrict__ b_g2,
             const float* __restrict__ alphap,
             int N, int M)
{
    extern __shared__ char gsm[];
    const uint32_t sbase = smem_u32(gsm);
    const int tid = threadIdx.x, lane = tid & 31, wid = tid >> 5;
    const int wm = wid & 1, wn = wid >> 1;     // 2 x 4 warps -> 32x128
    const int m0 = blockIdx.x * 32;

    // ---- W1 pipeline prologue: stages 0,1 ----
    #pragma unroll
    for (int pre = 0; pre < 2; ++pre) {
        uint32_t wb = sbase + GA_SM + pre * GW_STG;
        #pragma unroll
        for (int i = 0; i < 4; ++i) {
            int u = tid + i * 256;
            int rowB = u >> 3, kc = (u & 7) * 8;
            CP_ASYNC16(wb + swz((uint32_t)rowB, (uint32_t)kc * 2),
                       (const void*)(g_W1 + (size_t)rowB * KB_ + pre * 64 + kc));
        }
        CP_COMMIT();
    }

    // ---- A: gather + convert ----
    {
        int r = tid >> 3, ch = tid & 7;
        int gr = m0 + r;
        const float4* src = nullptr;
        if (gr < M) {
            int b = gr / N, j = gr - b * N;
            int p = g_idx[j];
            src = (const float4*)(tokens + ((size_t)b * P_ + p) * FULL_ + SLS_ + ch * 64);
        }
        __half2 hv[32];
        #pragma unroll
        for (int i = 0; i < 16; ++i) {
            float4 v = src ? src[i] : make_float4(0.f, 0.f, 0.f, 0.f);
            hv[2 * i]     = __half2(__float2half(v.x), __float2half(v.y));
            hv[2 * i + 1] = __half2(__float2half(v.z), __float2half(v.w));
        }
        #pragma unroll
        for (int u = 0; u < 8; ++u) {
            uint32_t o = (uint32_t)(ch * 4096) + swz((uint32_t)r, (uint32_t)(u * 16));
            *(uint4*)(gsm + o) = *(uint4*)&hv[u * 4];
        }
        __half* gdst = g_A2 + (size_t)gr * KB_ + ch * 64;
        #pragma unroll
        for (int u = 0; u < 8; ++u)
            *(uint4*)(gdst + u * 8) = *(uint4*)&hv[u * 4];
    }

    // ---- MMA: h[32,128] = A @ W1^T, W1 pipelined ----
    float acc[2][2][4];
    #pragma unroll
    for (int p = 0; p < 2; ++p)
        #pragma unroll
        for (int j = 0; j < 2; ++j)
            #pragma unroll
            for (int q = 0; q < 4; ++q) acc[p][j][q] = 0.f;

    #pragma unroll 1
    for (int s = 0; s < 8; ++s) {
        CP_WAIT1();
        __syncthreads();
        if (s + 2 < 8) {
            uint32_t wb = sbase + GA_SM + ((s + 2) % 3) * GW_STG;
            #pragma unroll
            for (int i = 0; i < 4; ++i) {
                int u = tid + i * 256;
                int rowB = u >> 3, kc = (u & 7) * 8;
                CP_ASYNC16(wb + swz((uint32_t)rowB, (uint32_t)kc * 2),
                           (const void*)(g_W1 + (size_t)rowB * KB_ + (s + 2) * 64 + kc));
            }
        }
        CP_COMMIT();

        const uint32_t aBase = sbase + s * 4096;
        const uint32_t bBase = sbase + GA_SM + (s % 3) * GW_STG;
        const uint32_t rowA = wm * 16 + (lane & 15);
        #pragma unroll
        for (int kk = 0; kk < 4; ++kk) {
            uint32_t a[4];
            uint32_t bcA = kk * 32 + (lane >> 4) * 16;
            LDSM4(a[0], a[1], a[2], a[3], aBase + swz(rowA, bcA));
            #pragma unroll
            for (int p = 0; p < 2; ++p) {
                uint32_t rowB = wn * 32 + p * 16 + ((lane >> 4) & 1) * 8 + (lane & 7);
                uint32_t bcB = kk * 32 + ((lane >> 3) & 1) * 16;
                uint32_t b0, b1, b2, b3;
                LDSM4(b0, b1, b2, b3, bBase + swz(rowB, bcB));
                MMA16816(acc[p][0], a, b0, b1);
                MMA16816(acc[p][1], a, b2, b3);
            }
        }
        __syncthreads();
    }

    // ---- h tile -> smem ----
    float* hs = (float*)gsm;   // [32][132]
    {
        int r0h = wm * 16 + (lane >> 2);
        int cb  = wn * 32 + (lane & 3) * 2;
        #pragma unroll
        for (int p = 0; p < 2; ++p)
            #pragma unroll
            for (int j = 0; j < 2; ++j) {
                int cc = cb + p * 16 + j * 8;
                hs[r0h * 132 + cc]           = acc[p][j][0];
                hs[r0h * 132 + cc + 1]       = acc[p][j][1];
                hs[(r0h + 8) * 132 + cc]     = acc[p][j][2];
                hs[(r0h + 8) * 132 + cc + 1] = acc[p][j][3];
            }
    }
    __syncthreads();

    // ---- GELU + dot(w2) + sigmoid -> scale ----
    float aw = 1.f / (1.f + expf(-alphap[0]));
    #pragma unroll
    for (int rr = 0; rr < 4; ++rr) {
        int r = wid * 4 + rr;
        float s = 0.f;
        #pragma unroll
        for (int q = 0; q < 4; ++q) {
            int cc = lane + 32 * q;
            float x = hs[r * 132 + cc] + b_g1[cc];
            float h = 0.5f * x * (1.f + erff(x * 0.70710678118654752f));
            s += h * W_g2[cc];
        }
        #pragma unroll
        for (int o = 16; o >= 1; o >>= 1) s += __shfl_xor_sync(0xffffffffu, s, o);
        if (lane == 0) {
            float gate = 1.f / (1.f + expf(-(s + b_g2[0])));
            g_scale[m0 + r] = gate * aw + (1.f - aw);
        }
    }
}

// =====================================================================
// K3: main HMMA GEMM C[Mpad,3072] = A@B^T (K=512), scaled epilogue
//     (streaming stores) + pentachoron partials atomicAdd'ed into d_out.
// =====================================================================
#define TILE_B    16384
#define STAGE_B2  (2 * TILE_B)
#define NSTAGE    3
#define GEMM_SMEM (NSTAGE * STAGE_B2)    // 98304
#define NS        (KB_ / 64)             // 8

__global__ void __launch_bounds__(256, 2)
k_gemm_mma(float* __restrict__ out, int M)
{
    extern __shared__ char smem[];
    const uint32_t sb = smem_u32(smem);
    const int tid = threadIdx.x, lane = tid & 31;
    const int wid = tid >> 5;
    const int wm = wid & 3, wn = wid >> 2;          // 4 x 2 warp grid
    const int m0 = blockIdx.y * 128;
    const int n0 = blockIdx.x * 128;

    const __half* Ag = g_A2 + (size_t)m0 * KB_;
    const __half* Bg = g_B2 + (size_t)n0 * KB_;

    const int ldRow = tid >> 3, ldCh = (tid & 7) * 8;

    float acc[2][8][4];
    #pragma unroll
    for (int h = 0; h < 2; ++h)
        #pragma unroll
        for (int j = 0; j < 8; ++j)
            #pragma unroll
            for (int q = 0; q < 4; ++q) acc[h][j][q] = 0.f;

    #pragma unroll
    for (int pre = 0; pre < 2; ++pre) {
        uint32_t base = sb + pre * STAGE_B2;
        #pragma unroll
        for (int i = 0; i < 4; ++i) {
            int row = ldRow + i * 32;
            uint32_t doff = swz(row, ldCh * 2);
            CP_ASYNC16(base + doff, (const void*)(Ag + (size_t)row * KB_ + pre * 64 + ldCh));
            CP_ASYNC16(base + TILE_B + doff, (const void*)(Bg + (size_t)row * KB_ + pre * 64 + ldCh));
        }
        CP_COMMIT();
    }

    #pragma unroll 1
    for (int s = 0; s < NS; ++s) {
        CP_WAIT1();
        __syncthreads();
        if (s + 2 < NS) {
            uint32_t base = sb + ((s + 2) % NSTAGE) * STAGE_B2;
            #pragma unroll
            for (int i = 0; i < 4; ++i) {
                int row = ldRow + i * 32;
                uint32_t doff = swz(row, ldCh * 2);
                CP_ASYNC16(base + doff, (const void*)(Ag + (size_t)row * KB_ + (s + 2) * 64 + ldCh));
                CP_ASYNC16(base + TILE_B + doff, (const void*)(Bg + (size_t)row * KB_ + (s + 2) * 64 + ldCh));
            }
        }
        CP_COMMIT();

        const uint32_t stg = sb + (s % NSTAGE) * STAGE_B2;
        const uint32_t rowA0 = wm * 32 + (lane & 15);
        const uint32_t aRB0 = stg + rowA0 * 128, xrA0 = (rowA0 & 7u) << 4;
        const uint32_t aRB1 = aRB0 + 16 * 128;
        #pragma unroll
        for (int kk = 0; kk < 4; ++kk) {
            uint32_t a0[4], a1[4];
            uint32_t bcA = kk * 32 + (lane >> 4) * 16;
            LDSM4(a0[0], a0[1], a0[2], a0[3], aRB0 + (bcA ^ xrA0));
            LDSM4(a1[0], a1[1], a1[2], a1[3], aRB1 + (bcA ^ xrA0));
            #pragma unroll
            for (int p = 0; p < 4; ++p) {
                uint32_t rowB = wn * 64 + p * 16 + ((lane >> 4) & 1) * 8 + (lane & 7);
                uint32_t bcB = kk * 32 + ((lane >> 3) & 1) * 16;
                uint32_t b0, b1, b2, b3;
                LDSM4(b0, b1, b2, b3, stg + TILE_B + swz(rowB, bcB));
                MMA16816(acc[0][2 * p],     a0, b0, b1);
                MMA16816(acc[0][2 * p + 1], a0, b2, b3);
                MMA16816(acc[1][2 * p],     a1, b0, b1);
                MMA16816(acc[1][2 * p + 1], a1, b2, b3);
            }
        }
        __syncthreads();
    }

    // ---- dirs slice into smem ----
    float* ds = (float*)smem;            // [5][128]
    const int ncol0 = n0 & 1023;
    for (int i = tid; i < 640; i += 256) {
        int v = i >> 7, l = i & 127;
        ds[i] = g_dirs[v * EDIM_ + ncol0 + l];
    }
    __syncthreads();

    // ---- epilogue: scale, streaming store, proj partials -> atomicAdd ----
    const int sel  = n0 >> 10;
    const int ncolB = ncol0 + wn * 64;
    float* outM = out + (size_t)sel * M * EDIM_;
    float* projM = out + (size_t)3 * M * EDIM_ + (size_t)sel * 5 * M;
    #pragma unroll
    for (int h = 0; h < 2; ++h) {
        #pragma unroll
        for (int rr = 0; rr < 2; ++rr) {
            int grow = m0 + wm * 32 + h * 16 + rr * 8 + (lane >> 2);
            float sc = g_scale[grow];
            bool ok = grow < M;
            float* orow = outM + (size_t)grow * EDIM_ + ncolB + 2 * (lane & 3);
            float p0 = 0.f, p1 = 0.f, p2 = 0.f, p3 = 0.f, p4 = 0.f;
            #pragma unroll
            for (int j = 0; j < 8; ++j) {
                float c0 = acc[h][j][2 * rr] * sc;
                float c1 = acc[h][j][2 * rr + 1] * sc;
                if (ok) __stcs((float2*)(orow + j * 8), make_float2(c0, c1));
                int lc = wn * 64 + j * 8 + 2 * (lane & 3);
                p0 += c0 * ds[lc]       + c1 * ds[lc + 1];
                p1 += c0 * ds[128 + lc] + c1 * ds[128 + lc + 1];
                p2 += c0 * ds[256 + lc] + c1 * ds[256 + lc + 1];
                p3 += c0 * ds[384 + lc] + c1 * ds[384 + lc + 1];
                p4 += c0 * ds[512 + lc] + c1 * ds[512 + lc + 1];
            }
            p0 += __shfl_xor_sync(0xffffffffu, p0, 1); p0 += __shfl_xor_sync(0xffffffffu, p0, 2);
            p1 += __shfl_xor_sync(0xffffffffu, p1, 1); p1 += __shfl_xor_sync(0xffffffffu, p1, 2);
            p2 += __shfl_xor_sync(0xffffffffu, p2, 1); p2 += __shfl_xor_sync(0xffffffffu, p2, 2);
            p3 += __shfl_xor_sync(0xffffffffu, p3, 1); p3 += __shfl_xor_sync(0xffffffffu, p3, 2);
            p4 += __shfl_xor_sync(0xffffffffu, p4, 1); p4 += __shfl_xor_sync(0xffffffffu, p4, 2);
            if (ok && (lane & 3) == 0) {
                atomicAdd(projM + 0 * (size_t)M + grow, p0);
                atomicAdd(projM + 1 * (size_t)M + grow, p1);
                atomicAdd(projM + 2 * (size_t)M + grow, p2);
                atomicAdd(projM + 3 * (size_t)M + grow, p3);
                atomicAdd(projM + 4 * (size_t)M + grow, p4);
            }
        }
    }
}

// =====================================================================
extern "C" void kernel_launch(void* const* d_in, const int* in_sizes, int n_in,
                              void* d_out, int out_size)
{
    const float* tokens = (const float*)d_in[0];
    const float* fps    = (const float*)d_in[1];
    const float* W_g1   = (const float*)d_in[2];
    const float* b_g1   = (const float*)d_in[3];
    const float* W_g2   = (const float*)d_in[4];
    const float* b_g2   = (const float*)d_in[5];
    const float* alpha  = (const float*)d_in[6];
    const float* Wq     = (const float*)d_in[7];
    const float* Wk     = (const float*)d_in[8];
    const float* Wv     = (const float*)d_in[9];
    const float* penta  = (const float*)d_in[10];

    int N = out_size / 12348;       // per token: 3*1024 QKV + 3*5 projections
    if (N <= 0) return;
    int M = 4 * N;
    int Mpad = (M + 127) & ~127;
    float* out = (float*)d_out;

    cudaFuncSetAttribute(k_gemm_mma, cudaFuncAttributeMaxDynamicSharedMemorySize, GEMM_SMEM);
    cudaFuncSetAttribute(k_gategather, cudaFuncAttributeMaxDynamicSharedMemorySize, GSMEM);

    int zblocks = (int)((15LL * M / 4 + 4095) / 4096);   // 4096 float4 per block
    k_prep<<<101 + zblocks, 1024>>>(fps, penta, Wq, Wk, Wv, W_g1, out, M);
    k_gategather<<<Mpad / 32, 256, GSMEM>>>(tokens, b_g1, W_g2, b_g2, alpha, N, M);
    dim3 g3(24, Mpad / 128);
    k_gemm_mma<<<g3, 256, GEMM_SMEM>>>(out, M);
}

// round 15
// speedup vs baseline: 1.0358x; 1.0064x over previous
#include <cuda_runtime.h>
#include <cuda_fp16.h>
#include <cstdint>
#include <math.h>

// ---------------- problem constants ----------------
#define B_      4
#define P_      4096
#define FULL_   4096
#define SLICE_  512
#define EDIM_   1024
#define SLS_    1024          // slice start
#define FPMIN_  0.1875f
#define FPMAX_  0.4375f
#define KB_     512           // K for all GEMMs (fp16 hi only)

// ---------------- scratch (no allocs allowed) ----------------
__device__ __align__(16) __half g_A2[(size_t)B_ * P_ * KB_];    // gathered slice, fp16
__device__ __align__(16) __half g_B2[(size_t)3 * EDIM_ * KB_];  // Wq|Wk|Wv fp16
__device__ __align__(16) __half g_W1[(size_t)128 * KB_];        // W_g1 fp16
__device__ float g_scale[B_ * P_ + 256];
__device__ int   g_idx[P_];
__device__ __align__(16) float g_dirs[5 * EDIM_];

// ---------------- PTX helpers (sm_103-base-safe only) ----------------
__device__ __forceinline__ uint32_t smem_u32(const void* p) {
    uint32_t a; asm("{ .reg .u64 t; cvta.to.shared.u64 t, %1; cvt.u32.u64 %0, t; }" : "=r"(a) : "l"(p)); return a;
}
#define CP_ASYNC16(dst, src) \
    asm volatile("cp.async.cg.shared.global [%0], [%1], 16;" :: "r"(dst), "l"(src))
#define CP_COMMIT() asm volatile("cp.async.commit_group;" ::: "memory")
#define CP_WAIT1()  asm volatile("cp.async.wait_group 1;" ::: "memory")

#define LDSM4(r0, r1, r2, r3, a) \
    asm volatile("ldmatrix.sync.aligned.m8n8.x4.shared.b16 {%0,%1,%2,%3}, [%4];" \
        : "=r"(r0), "=r"(r1), "=r"(r2), "=r"(r3) : "r"(a))

#define MMA16816(c, a, b0, b1) \
    asm volatile("mma.sync.aligned.m16n8k16.row.col.f32.f16.f16.f32 " \
        "{%0,%1,%2,%3},{%4,%5,%6,%7},{%8,%9},{%0,%1,%2,%3};" \
        : "+f"((c)[0]), "+f"((c)[1]), "+f"((c)[2]), "+f"((c)[3]) \
        : "r"((a)[0]), "r"((a)[1]), "r"((a)[2]), "r"((a)[3]), "r"(b0), "r"(b1))

__device__ __forceinline__ uint32_t swz(uint32_t row, uint32_t bytecol) {
    return row * 128u + (bytecol ^ ((row & 7u) << 4));
}

// =====================================================================
// K1: merged prep, 512 threads/block, 2 quads/thread.
//   Block 0: compaction (warp-shuffle scan over 1024 fps slots via 2
//            rounds folded into 512 threads x 8 fps) + dirs.
//   Blocks 1..8:      W_g1 -> g_W1 fp16        (16384 quads)
//   Blocks 9..392:    Wq|Wk|Wv -> g_B2 fp16    (393216 quads)
//   Blocks 393+:      zero projection region of out (2048 f4/block)
// =====================================================================
__global__ void k_prep(const float* __restrict__ fps,
                       const float* __restrict__ penta,
                       const float* __restrict__ Wq,
                       const float* __restrict__ Wk,
                       const float* __restrict__ Wv,
                       const float* __restrict__ W_g1,
                       float* __restrict__ out, int M)
{
    int t = threadIdx.x;   // 512
    int bid = blockIdx.x;
    if (bid >= 393) {
        long long base4 = (long long)(bid - 393) * 2048 + t;
        long long tot4 = (long long)15 * M / 4;
        float4* dst = (float4*)(out + (size_t)3 * M * EDIM_);
        #pragma unroll
        for (int i = 0; i < 4; ++i) {
            long long i4 = base4 + (long long)i * 512;
            if (i4 < tot4) dst[i4] = make_float4(0.f, 0.f, 0.f, 0.f);
        }
        return;
    }
    if (bid >= 9) {                        // B2: 393216 quads, 1024/block
        int id0 = (bid - 9) * 1024 + t;
        float4 v[2];
        int ids[2];
        #pragma unroll
        for (int i = 0; i < 2; ++i) {
            int id = id0 + i * 512;        // exact: 384 blocks
            ids[i] = id;
            int n  = id >> 7;
            int k4 = (id & 127) * 4;
            const float* W;
            int nn;
            if (n < 1024)      { W = Wq; nn = n; }
            else if (n < 2048) { W = Wk; nn = n - 1024; }
            else               { W = Wv; nn = n - 2048; }
            v[i] = *(const float4*)(W + (size_t)nn * 512 + k4);
        }
        #pragma unroll
        for (int i = 0; i < 2; ++i) {
            int n  = ids[i] >> 7;
            int k4 = (ids[i] & 127) * 4;
            __half2* d = (__half2*)(g_B2 + (size_t)n * KB_ + k4);
            d[0] = __half2(__float2half(v[i].x), __float2half(v[i].y));
            d[1] = __half2(__float2half(v[i].z), __float2half(v[i].w));
        }
        return;
    }
    if (bid >= 1) {                        // W1: 16384 quads, 2048/block
        int id0 = (bid - 1) * 2048 + t;
        float4 v[4];
        #pragma unroll
        for (int i = 0; i < 4; ++i) {
            int id = id0 + i * 512;        // exact: 8 blocks
            int n  = id >> 7;
            int k4 = (id & 127) * 4;
            v[i] = *(const float4*)(W_g1 + (size_t)n * 512 + k4);
        }
        #pragma unroll
        for (int i = 0; i < 4; ++i) {
            int id = id0 + i * 512;
            int n  = id >> 7;
            int k4 = (id & 127) * 4;
            __half2* d = (__half2*)(g_W1 + (size_t)n * KB_ + k4);
            d[0] = __half2(__float2half(v[i].x), __float2half(v[i].y));
            d[1] = __half2(__float2half(v[i].z), __float2half(v[i].w));
        }
        return;
    }

    // ---- block 0: compaction via warp-shuffle scan (8 fps/thread) ----
    __shared__ int warp_s[16];
    int lane = t & 31, w = t >> 5;        // 16 warps
    float4 f0 = *(const float4*)(fps + t * 8);
    float4 f1 = *(const float4*)(fps + t * 8 + 4);
    unsigned mm[8];
    mm[0] = (f0.x >= FPMIN_ && f0.x < FPMAX_) ? 1u : 0u;
    mm[1] = (f0.y >= FPMIN_ && f0.y < FPMAX_) ? 1u : 0u;
    mm[2] = (f0.z >= FPMIN_ && f0.z < FPMAX_) ? 1u : 0u;
    mm[3] = (f0.w >= FPMIN_ && f0.w < FPMAX_) ? 1u : 0u;
    mm[4] = (f1.x >= FPMIN_ && f1.x < FPMAX_) ? 1u : 0u;
    mm[5] = (f1.y >= FPMIN_ && f1.y < FPMAX_) ? 1u : 0u;
    mm[6] = (f1.z >= FPMIN_ && f1.z < FPMAX_) ? 1u : 0u;
    mm[7] = (f1.w >= FPMIN_ && f1.w < FPMAX_) ? 1u : 0u;
    int cnt = 0;
    #pragma unroll
    for (int i = 0; i < 8; ++i) cnt += (int)mm[i];
    int inc = cnt;
    #pragma unroll
    for (int o = 1; o < 32; o <<= 1) {
        int x = __shfl_up_sync(0xffffffffu, inc, o);
        if (lane >= o) inc += x;
    }
    if (lane == 31) warp_s[w] = inc;
    __syncthreads();
    if (w == 0 && lane < 16) {
        int v = warp_s[lane];
        int iv = v;
        #pragma unroll
        for (int o = 1; o < 16; o <<= 1) {
            int x = __shfl_up_sync(0x0000ffffu, iv, o);
            if (lane >= o) iv += x;
        }
        warp_s[lane] = iv - v;   // exclusive warp base
    }
    __syncthreads();
    int off = warp_s[w] + inc - cnt;
    int base = t * 8;
    #pragma unroll
    for (int i = 0; i < 8; ++i)
        if (mm[i]) g_idx[off++] = base + i;

    // ---- dirs normalization (5 warps) ----
    if (t < 160) {
        int wv = t >> 5, ln = t & 31;
        float s = 0.f;
        #pragma unroll
        for (int kk = 0; kk < 32; ++kk) {
            float x = penta[wv * EDIM_ + kk * 32 + ln];
            s += x * x;
        }
        #pragma unroll
        for (int o = 16; o >= 1; o >>= 1) s += __shfl_xor_sync(0xffffffffu, s, o);
        float inv = rsqrtf(s);
        #pragma unroll
        for (int kk = 0; kk < 32; ++kk) {
            int id = wv * EDIM_ + kk * 32 + ln;
            g_dirs[id] = penta[id] * inv;
        }
    }
}

// =====================================================================
// K2: fused gather + gate. 32 rows/block, 256 thr, 2 CTAs/SM. (round-10)
// smem: A resident 32KB | W1 3-stage pipeline 3 x 16KB -> 80KB total
// =====================================================================
#define GA_SM   32768
#define GW_STG  16384
#define GSMEM   (GA_SM + 3 * GW_STG)     // 81920
__global__ void __launch_bounds__(256, 2)
k_gategather(const float* __restrict__ tokens,
             const float* __restrict__ b_g1,
             const float* __restrict__ W_g2,
             const float* __restrict__ b_g2,
             const float* __restrict__ alphap,
             int N, int M)
{
    extern __shared__ char gsm[];
    const uint32_t sbase = smem_u32(gsm);
    const int tid = threadIdx.x, lane = tid & 31, wid = tid >> 5;
    const int wm = wid & 1, wn = wid >> 1;     // 2 x 4 warps -> 32x128
    const int m0 = blockIdx.x * 32;

    // ---- W1 pipeline prologue: stages 0,1 ----
    #pragma unroll
    for (int pre = 0; pre < 2; ++pre) {
        uint32_t wb = sbase + GA_SM + pre * GW_STG;
        #pragma unroll
        for (int i = 0; i < 4; ++i) {
            int u = tid + i * 256;
            int rowB = u >> 3, kc = (u & 7) * 8;
            CP_ASYNC16(wb + swz((uint32_t)rowB, (uint32_t)kc * 2),
                       (const void*)(g_W1 + (size_t)rowB * KB_ + pre * 64 + kc));
        }
        CP_COMMIT();
    }

    // ---- A: gather + convert ----
    {
        int r = tid >> 3, ch = tid & 7;
        int gr = m0 + r;
        const float4* src = nullptr;
        if (gr < M) {
            int b = gr / N, j = gr - b * N;
            int p = g_idx[j];
            src = (const float4*)(tokens + ((size_t)b * P_ + p) * FULL_ + SLS_ + ch * 64);
        }
        __half2 hv[32];
        #pragma unroll
        for (int i = 0; i < 16; ++i) {
            float4 v = src ? src[i] : make_float4(0.f, 0.f, 0.f, 0.f);
            hv[2 * i]     = __half2(__float2half(v.x), __float2half(v.y));
            hv[2 * i + 1] = __half2(__float2half(v.z), __float2half(v.w));
        }
        #pragma unroll
        for (int u = 0; u < 8; ++u) {
            uint32_t o = (uint32_t)(ch * 4096) + swz((uint32_t)r, (uint32_t)(u * 16));
            *(uint4*)(gsm + o) = *(uint4*)&hv[u * 4];
        }
        __half* gdst = g_A2 + (size_t)gr * KB_ + ch * 64;
        #pragma unroll
        for (int u = 0; u < 8; ++u)
            *(uint4*)(gdst + u * 8) = *(uint4*)&hv[u * 4];
    }

    // ---- MMA: h[32,128] = A @ W1^T, W1 pipelined ----
    float acc[2][2][4];
    #pragma unroll
    for (int p = 0; p < 2; ++p)
        #pragma unroll
        for (int j = 0; j < 2; ++j)
            #pragma unroll
            for (int q = 0; q < 4; ++q) acc[p][j][q] = 0.f;

    #pragma unroll 1
    for (int s = 0; s < 8; ++s) {
        CP_WAIT1();
        __syncthreads();
        if (s + 2 < 8) {
            uint32_t wb = sbase + GA_SM + ((s + 2) % 3) * GW_STG;
            #pragma unroll
            for (int i = 0; i < 4; ++i) {
                int u = tid + i * 256;
                int rowB = u >> 3, kc = (u & 7) * 8;
                CP_ASYNC16(wb + swz((uint32_t)rowB, (uint32_t)kc * 2),
                           (const void*)(g_W1 + (size_t)rowB * KB_ + (s + 2) * 64 + kc));
            }
        }
        CP_COMMIT();

        const uint32_t aBase = sbase + s * 4096;
        const uint32_t bBase = sbase + GA_SM + (s % 3) * GW_STG;
        const uint32_t rowA = wm * 16 + (lane & 15);
        #pragma unroll
        for (int kk = 0; kk < 4; ++kk) {
            uint32_t a[4];
            uint32_t bcA = kk * 32 + (lane >> 4) * 16;
            LDSM4(a[0], a[1], a[2], a[3], aBase + swz(rowA, bcA));
            #pragma unroll
            for (int p = 0; p < 2; ++p) {
                uint32_t rowB = wn * 32 + p * 16 + ((lane >> 4) & 1) * 8 + (lane & 7);
                uint32_t bcB = kk * 32 + ((lane >> 3) & 1) * 16;
                uint32_t b0, b1, b2, b3;
                LDSM4(b0, b1, b2, b3, bBase + swz(rowB, bcB));
                MMA16816(acc[p][0], a, b0, b1);
                MMA16816(acc[p][1], a, b2, b3);
            }
        }
        __syncthreads();
    }

    // ---- h tile -> smem ----
    float* hs = (float*)gsm;   // [32][132]
    {
        int r0h = wm * 16 + (lane >> 2);
        int cb  = wn * 32 + (lane & 3) * 2;
        #pragma unroll
        for (int p = 0; p < 2; ++p)
            #pragma unroll
            for (int j = 0; j < 2; ++j) {
                int cc = cb + p * 16 + j * 8;
                hs[r0h * 132 + cc]           = acc[p][j][0];
                hs[r0h * 132 + cc + 1]       = acc[p][j][1];
                hs[(r0h + 8) * 132 + cc]     = acc[p][j][2];
                hs[(r0h + 8) * 132 + cc + 1] = acc[p][j][3];
            }
    }
    __syncthreads();

    // ---- GELU + dot(w2) + sigmoid -> scale ----
    float aw = 1.f / (1.f + expf(-alphap[0]));
    #pragma unroll
    for (int rr = 0; rr < 4; ++rr) {
        int r = wid * 4 + rr;
        float s = 0.f;
        #pragma unroll
        for (int q = 0; q < 4; ++q) {
            int cc = lane + 32 * q;
            float x = hs[r * 132 + cc] + b_g1[cc];
            float h = 0.5f * x * (1.f + erff(x * 0.70710678118654752f));
            s += h * W_g2[cc];
        }
        #pragma unroll
        for (int o = 16; o >= 1; o >>= 1) s += __shfl_xor_sync(0xffffffffu, s, o);
        if (lane == 0) {
            float gate = 1.f / (1.f + expf(-(s + b_g2[0])));
            g_scale[m0 + r] = gate * aw + (1.f - aw);
        }
    }
}

// =====================================================================
// K3: main HMMA GEMM C[Mpad,3072] = A@B^T (K=512), scaled epilogue
//     (streaming stores) + pentachoron partials atomicAdd'ed into d_out.
//     dirs cached in a DEDICATED smem region (loaded in prologue; no
//     post-mainloop sync needed).
// =====================================================================
#define TILE_B    16384
#define STAGE_B2  (2 * TILE_B)
#define NSTAGE    3
#define DS_OFF    (NSTAGE * STAGE_B2)          // 98304
#define GEMM_SMEM (DS_OFF + 640 * 4)           // +2560 = 100864
#define NS        (KB_ / 64)                   // 8

__global__ void __launch_bounds__(256, 2)
k_gemm_mma(float* __restrict__ out, int M)
{
    extern __shared__ char smem[];
    const uint32_t sb = smem_u32(smem);
    const int tid = threadIdx.x, lane = tid & 31;
    const int wid = tid >> 5;
    const int wm = wid & 3, wn = wid >> 2;          // 4 x 2 warp grid
    const int m0 = blockIdx.y * 128;
    const int n0 = blockIdx.x * 128;

    const __half* Ag = g_A2 + (size_t)m0 * KB_;
    const __half* Bg = g_B2 + (size_t)n0 * KB_;

    const int ldRow = tid >> 3, ldCh = (tid & 7) * 8;

    // ---- dirs slice into dedicated smem (prologue; covered by the
    //      mainloop's first __syncthreads) ----
    float* ds = (float*)(smem + DS_OFF);   // [5][128]
    const int ncol0 = n0 & 1023;
    {
        int i = tid;                        // 256 threads cover 640 in 3 steps
        #pragma unroll
        for (int rpt = 0; rpt < 3; ++rpt) {
            if (i < 640) {
                int v = i / 128, l = i - v * 128;
                ds[i] = g_dirs[v * EDIM_ + ncol0 + l];
            }
            i += 256;
        }
    }

    float acc[2][8][4];
    #pragma unroll
    for (int h = 0; h < 2; ++h)
        #pragma unroll
        for (int j = 0; j < 8; ++j)
            #pragma unroll
            for (int q = 0; q < 4; ++q) acc[h][j][q] = 0.f;

    #pragma unroll
    for (int pre = 0; pre < 2; ++pre) {
        uint32_t base = sb + pre * STAGE_B2;
        #pragma unroll
        for (int i = 0; i < 4; ++i) {
            int row = ldRow + i * 32;
            uint32_t doff = swz(row, ldCh * 2);
            CP_ASYNC16(base + doff, (const void*)(Ag + (size_t)row * KB_ + pre * 64 + ldCh));
            CP_ASYNC16(base + TILE_B + doff, (const void*)(Bg + (size_t)row * KB_ + pre * 64 + ldCh));
        }
        CP_COMMIT();
    }

    #pragma unroll 1
    for (int s = 0; s < NS; ++s) {
        CP_WAIT1();
        __syncthreads();
        if (s + 2 < NS) {
            uint32_t base = sb + ((s + 2) % NSTAGE) * STAGE_B2;
            #pragma unroll
            for (int i = 0; i < 4; ++i) {
                int row = ldRow + i * 32;
                uint32_t doff = swz(row, ldCh * 2);
                CP_ASYNC16(base + doff, (const void*)(Ag + (size_t)row * KB_ + (s + 2) * 64 + ldCh));
                CP_ASYNC16(base + TILE_B + doff, (const void*)(Bg + (size_t)row * KB_ + (s + 2) * 64 + ldCh));
            }
        }
        CP_COMMIT();

        const uint32_t stg = sb + (s % NSTAGE) * STAGE_B2;
        const uint32_t rowA0 = wm * 32 + (lane & 15);
        const uint32_t aRB0 = stg + rowA0 * 128, xrA0 = (rowA0 & 7u) << 4;
        const uint32_t aRB1 = aRB0 + 16 * 128;
        #pragma unroll
        for (int kk = 0; kk < 4; ++kk) {
            uint32_t a0[4], a1[4];
            uint32_t bcA = kk * 32 + (lane >> 4) * 16;
            LDSM4(a0[0], a0[1], a0[2], a0[3], aRB0 + (bcA ^ xrA0));
            LDSM4(a1[0], a1[1], a1[2], a1[3], aRB1 + (bcA ^ xrA0));
            #pragma unroll
            for (int p = 0; p < 4; ++p) {
                uint32_t rowB = wn * 64 + p * 16 + ((lane >> 4) & 1) * 8 + (lane & 7);
                uint32_t bcB = kk * 32 + ((lane >> 3) & 1) * 16;
                uint32_t b0, b1, b2, b3;
                LDSM4(b0, b1, b2, b3, stg + TILE_B + swz(rowB, bcB));
                MMA16816(acc[0][2 * p],     a0, b0, b1);
                MMA16816(acc[0][2 * p + 1], a0, b2, b3);
                MMA16816(acc[1][2 * p],     a1, b0, b1);
                MMA16816(acc[1][2 * p + 1], a1, b2, b3);
            }
        }
        if (s + 1 < NS) __syncthreads();
    }

    // ---- epilogue: scale, streaming store, proj partials -> atomicAdd ----
    const int sel  = n0 >> 10;
    const int ncolB = ncol0 + wn * 64;
    float* outM = out + (size_t)sel * M * EDIM_;
    float* projM = out + (size_t)3 * M * EDIM_ + (size_t)sel * 5 * M;
    #pragma unroll
    for (int h = 0; h < 2; ++h) {
        #pragma unroll
        for (int rr = 0; rr < 2; ++rr) {
            int grow = m0 + wm * 32 + h * 16 + rr * 8 + (lane >> 2);
            float sc = g_scale[grow];
            bool ok = grow < M;
            float* orow = outM + (size_t)grow * EDIM_ + ncolB + 2 * (lane & 3);
            float p0 = 0.f, p1 = 0.f, p2 = 0.f, p3 = 0.f, p4 = 0.f;
            #pragma unroll
            for (int j = 0; j < 8; ++j) {
                float c0 = acc[h][j][2 * rr] * sc;
                float c1 = acc[h][j][2 * rr + 1] * sc;
                if (ok) __stcs((float2*)(orow + j * 8), make_float2(c0, c1));
                int lc = wn * 64 + j * 8 + 2 * (lane & 3);
                p0 += c0 * ds[lc]       + c1 * ds[lc + 1];
                p1 += c0 * ds[128 + lc] + c1 * ds[128 + lc + 1];
                p2 += c0 * ds[256 + lc] + c1 * ds[256 + lc + 1];
                p3 += c0 * ds[384 + lc] + c1 * ds[384 + lc + 1];
                p4 += c0 * ds[512 + lc] + c1 * ds[512 + lc + 1];
            }
            p0 += __shfl_xor_sync(0xffffffffu, p0, 1); p0 += __shfl_xor_sync(0xffffffffu, p0, 2);
            p1 += __shfl_xor_sync(0xffffffffu, p1, 1); p1 += __shfl_xor_sync(0xffffffffu, p1, 2);
            p2 += __shfl_xor_sync(0xffffffffu, p2, 1); p2 += __shfl_xor_sync(0xffffffffu, p2, 2);
            p3 += __shfl_xor_sync(0xffffffffu, p3, 1); p3 += __shfl_xor_sync(0xffffffffu, p3, 2);
            p4 += __shfl_xor_sync(0xffffffffu, p4, 1); p4 += __shfl_xor_sync(0xffffffffu, p4, 2);
            if (ok && (lane & 3) == 0) {
                atomicAdd(projM + 0 * (size_t)M + grow, p0);
                atomicAdd(projM + 1 * (size_t)M + grow, p1);
                atomicAdd(projM + 2 * (size_t)M + grow, p2);
                atomicAdd(projM + 3 * (size_t)M + grow, p3);
                atomicAdd(projM + 4 * (size_t)M + grow, p4);
            }
        }
    }
}

// =====================================================================
extern "C" void kernel_launch(void* const* d_in, const int* in_sizes, int n_in,
                              void* d_out, int out_size)
{
    const float* tokens = (const float*)d_in[0];
    const float* fps    = (const float*)d_in[1];
    const float* W_g1   = (const float*)d_in[2];
    const float* b_g1   = (const float*)d_in[3];
    const float* W_g2   = (const float*)d_in[4];
    const float* b_g2   = (const float*)d_in[5];
    const float* alpha  = (const float*)d_in[6];
    const float* Wq     = (const float*)d_in[7];
    const float* Wk     = (const float*)d_in[8];
    const float* Wv     = (const float*)d_in[9];
    const float* penta  = (const float*)d_in[10];

    int N = out_size / 12348;       // per token: 3*1024 QKV + 3*5 projections
    if (N <= 0) return;
    int M = 4 * N;
    int Mpad = (M + 127) & ~127;
    float* out = (float*)d_out;

    cudaFuncSetAttribute(k_gemm_mma, cudaFuncAttributeMaxDynamicSharedMemorySize, GEMM_SMEM);
    cudaFuncSetAttribute(k_gategather, cudaFuncAttributeMaxDynamicSharedMemorySize, GSMEM);

    int zblocks = (int)((15LL * M / 4 + 2047) / 2048);   // 2048 float4 per block
    k_prep<<<393 + zblocks, 512>>>(fps, penta, Wq, Wk, Wv, W_g1, out, M);
    k_gategather<<<Mpad / 32, 256, GSMEM>>>(tokens, b_g1, W_g2, b_g2, alpha, N, M);
    dim3 g3(24, Mpad / 128);
    k_gemm_mma<<<g3, 256, GEMM_SMEM>>>(out, M);
}